// round 5
// baseline (speedup 1.0000x reference)
#include <cuda_runtime.h>
#include <cuda_bf16.h>
#include <math.h>

#define BB   16
#define CIN  3
#define SS   16384
#define HID  64
#define NM   16
#define NL   4
#define NPSP 500
#define NPFR 200
#define ED   8
#define NCH  16          // split-K chunks for forward DFT

// ---------------- scratch (__device__ globals; no allocation) ----------------
__device__ float d_hA[BB * HID * SS];            // 64 MB
__device__ float d_hB[BB * HID * SS];            // 64 MB
__device__ float d_twc[SS * NM];                 // cos(2pi k s / S)
__device__ float d_tws[SS * NM];                 // sin(2pi k s / S)
__device__ float d_part[BB * NCH * HID * 32];    // split-K partials, 2 MB
__device__ float d_Cf[BB * HID * 32];            // combined scaled spectrum: 0..15 Re', 16..31 Im'
__device__ float d_sC[BB * SS];                  // per-position channel sums (for spatial hash)
__device__ int   d_idx[BB * SS];                 // spatial hash index
__device__ float d_Pall[NL * NPSP * HID];        // projected spatial patterns, all layers
__device__ float d_gw[BB];                       // gate weight w1 per batch

__device__ __forceinline__ const float* hbuf_c(int s) { return s ? d_hB : d_hA; }
__device__ __forceinline__ float*       hbuf(int s)   { return s ? d_hB : d_hA; }

// ---------------- twiddles ----------------
__global__ void k_init_tw() {
    int i = blockIdx.x * 256 + threadIdx.x;        // i < SS*NM
    int s = i / NM, k = i % NM;
    long m = ((long)s * (long)k) % SS;
    double th = 6.283185307179586476925286766559 * (double)m / (double)SS;
    d_twc[i] = (float)cos(th);
    d_tws[i] = (float)sin(th);
}

// ---------------- all-layer spatial pattern projection ----------------
__global__ void k_prep_all(const float* __restrict__ sp_emb, const float* __restrict__ sp_W,
                           const float* __restrict__ sp_b) {
    int i = blockIdx.x * 256 + threadIdx.x;        // NL*NPSP*HID = 128000
    if (i >= NL * NPSP * HID) return;
    int l = i / (NPSP * HID);
    int r = i - l * (NPSP * HID);
    int p = r / HID, c = r % HID;
    const float* e = sp_emb + (l * NPSP + p) * ED;
    const float* W = sp_W + l * ED * HID;
    float acc = sp_b[l * HID + c];
#pragma unroll
    for (int j = 0; j < ED; j++) acc = fmaf(e[j], W[j * HID + c], acc);
    d_Pall[i] = acc;
}

// ---------------- lift: h = x @ lift_W + lift_b ----------------
__global__ void k_lift(const float* __restrict__ x, const float* __restrict__ W,
                       const float* __restrict__ bias) {
    int i = blockIdx.x * 256 + threadIdx.x;        // over B*S
    int b = i >> 14;
    int s = i & (SS - 1);
    float x0 = x[(b * CIN + 0) * SS + s];
    float x1 = x[(b * CIN + 1) * SS + s];
    float x2 = x[(b * CIN + 2) * SS + s];
#pragma unroll
    for (int c = 0; c < HID; c++) {
        float v = fmaf(x0, __ldg(&W[0 * HID + c]),
                  fmaf(x1, __ldg(&W[1 * HID + c]),
                  fmaf(x2, __ldg(&W[2 * HID + c]), __ldg(&bias[c]))));
        d_hA[(b * HID + c) * SS + s] = v;
    }
}

// ---------------- forward DFT pass 1 (split-K, register-tiled) + channel sums ----------------
// grid (NCH, B), 256 threads. Each block: 1024 samples, all 64 channels, 32 cols.
// Thread: g = t&15 -> cols {2g, 2g+1};  c4 = t>>4 -> channels {4c4 .. 4c4+3}.
__global__ void __launch_bounds__(256) k_fwd1(int src) {
    __shared__ float sh_h[64][68];                 // [s_local][channel], padded
    __shared__ float sh_tw[64][32];                // [s_local][col] (0..15 cos, 16..31 sin)
    const float* h = hbuf_c(src);
    int chunk = blockIdx.x, b = blockIdx.y, t = threadIdx.x;
    int g = t & 15;
    int c4 = t >> 4;
    int s0 = chunk * (SS / NCH);

    float a00 = 0.f, a01 = 0.f, a10 = 0.f, a11 = 0.f;
    float a20 = 0.f, a21 = 0.f, a30 = 0.f, a31 = 0.f;

    int cs_ssl = t >> 2;                           // colsum: sample
    int cs_q   = t & 3;                            // colsum: channel quarter

    for (int piece = 0; piece < (SS / NCH) / 64; piece++) {
        int sp0 = s0 + piece * 64;
        // load h tile: 64 s x 64 c, float4 along s, transpose into [s][c]
        for (int u = t; u < 1024; u += 256) {
            int cc = u >> 4;
            int s4 = (u & 15) * 4;
            float4 v = *(const float4*)&h[(b * HID + cc) * SS + sp0 + s4];
            sh_h[s4 + 0][cc] = v.x; sh_h[s4 + 1][cc] = v.y;
            sh_h[s4 + 2][cc] = v.z; sh_h[s4 + 3][cc] = v.w;
        }
        // load twiddles: 64 s x (16 cos + 16 sin)
        for (int u = t; u < 512; u += 256) {
            int ssl = u >> 3, q = u & 7;
            float4 v;
            if (q < 4) v = *(const float4*)&d_twc[(sp0 + ssl) * NM + q * 4];
            else       v = *(const float4*)&d_tws[(sp0 + ssl) * NM + (q - 4) * 4];
            *(float4*)&sh_tw[ssl][q * 4] = v;
        }
        __syncthreads();

        // channel sums for spatial hash (deterministic fixed-order quad-shfl tree)
        {
            float cs = 0.f;
            const float* row = &sh_h[cs_ssl][cs_q * 16];
#pragma unroll
            for (int j = 0; j < 16; j++) cs += row[j];
            cs += __shfl_down_sync(0xFFFFFFFFu, cs, 2);
            cs += __shfl_down_sync(0xFFFFFFFFu, cs, 1);
            if (cs_q == 0) d_sC[b * SS + sp0 + cs_ssl] = cs;
        }

        // main FMA loop: 1 LDS.128 + 1 LDS.64 per 8 FMA
#pragma unroll 4
        for (int ssl = 0; ssl < 64; ssl++) {
            float t0 = sh_tw[ssl][g * 2 + 0];
            float t1 = sh_tw[ssl][g * 2 + 1];
            float4 hv = *(const float4*)&sh_h[ssl][c4 * 4];
            a00 = fmaf(hv.x, t0, a00); a01 = fmaf(hv.x, t1, a01);
            a10 = fmaf(hv.y, t0, a10); a11 = fmaf(hv.y, t1, a11);
            a20 = fmaf(hv.z, t0, a20); a21 = fmaf(hv.z, t1, a21);
            a30 = fmaf(hv.w, t0, a30); a31 = fmaf(hv.w, t1, a31);
        }
        __syncthreads();
    }
    float* p = &d_part[((b * NCH + chunk) * HID + c4 * 4) * 32 + g * 2];
    p[0 * 32 + 0] = a00; p[0 * 32 + 1] = a01;
    p[1 * 32 + 0] = a10; p[1 * 32 + 1] = a11;
    p[2 * 32 + 0] = a20; p[2 * 32 + 1] = a21;
    p[3 * 32 + 0] = a30; p[3 * 32 + 1] = a31;
}

// ---------------- merged per-batch kernel: DFT reduce + spatial hash + spectral mix + gate ----------------
__global__ void __launch_bounds__(256) k_mix(
        const float* __restrict__ fr_emb, const float* __restrict__ fr_W,
        const float* __restrict__ fr_b,
        const float* __restrict__ mhf_Wr, const float* __restrict__ mhf_Wi,
        const float* __restrict__ gW1, const float* __restrict__ gb1,
        const float* __restrict__ gW2, const float* __restrict__ gb2,
        int layer) {
    __shared__ float shX[HID * 32];                // 0..15 sum*cos (Re), 16..31 sum*sin (-Im)
    __shared__ float shMHre[HID * NM];
    __shared__ float shMHim[HID * NM];
    __shared__ float shFR[HID * NM];
    __shared__ int   hist[NPSP];
    __shared__ float shg[192];
    __shared__ float shhid[64];
    __shared__ float shw[3];
    __shared__ int   shmi[16];
    __shared__ int   sh_ifr;
    int b = blockIdx.x, t = threadIdx.x;

    for (int i = t; i < NPSP; i += 256) hist[i] = 0;

    // Phase A: deterministic reduction of split-K partials (fp64, fixed chunk order)
    for (int u = t; u < HID * 32; u += 256) {
        double acc = 0.0;
        const float* p = d_part + (b * NCH) * (HID * 32) + u;
        for (int ch = 0; ch < NCH; ch++) acc += (double)p[ch * HID * 32];
        shX[u] = (float)acc;
    }
    __syncthreads();

    // Phase B: spatial hash + histogram (int atomics in shared -> deterministic)
    {
        const float* sc = d_sC + b * SS;
        for (int s = t; s < SS; s += 256) {
            int a0 = max(s - 2, 0), a1 = max(s - 1, 0), a3 = min(s + 1, SS - 1);
            float w = ((sc[a0] + sc[a1]) + sc[s]) + sc[a3];
            int iv = (int)(w * 31.0f);
            int m = iv % NPSP; if (m < 0) m += NPSP;
            d_idx[b * SS + s] = m;
            atomicAdd(&hist[m], 1);
        }
    }

    // spectral magnitude hash (fixed channel order, fp64)
    if (t < 16) {
        double acc = 0.0;
        for (int c = 0; c < HID; c++) {
            double re = (double)shX[c * 32 + t];
            double im = (double)shX[c * 32 + 16 + t];
            acc += sqrt(re * re + im * im);
        }
        float mag = (float)(acc / 64.0);
        shmi[t] = (int)(mag * 1000.0f);
    }
    // multi-head Fourier mix
    for (int u = t; u < 1024; u += 256) {            // u = h*256 + o*16 + k
        int h_ = u >> 8, o = (u >> 4) & 15, k = u & 15;
        float ar = 0.f, ai = 0.f;
        const float* Wr = mhf_Wr + (((layer * 4 + h_) * 16) * 16 + o) * 16 + k;
        const float* Wi = mhf_Wi + (((layer * 4 + h_) * 16) * 16 + o) * 16 + k;
#pragma unroll
        for (int i = 0; i < 16; i++) {
            int cin = h_ * 16 + i;
            float re = shX[cin * 32 + k];
            float im = -shX[cin * 32 + 16 + k];
            float wr = Wr[i * 256];
            float wi = Wi[i * 256];
            ar = fmaf(re, wr, ar); ar = fmaf(-im, wi, ar);
            ai = fmaf(re, wi, ai); ai = fmaf(im, wr, ai);
        }
        int cout = h_ * 16 + o;
        shMHre[cout * 16 + k] = ar;
        shMHim[cout * 16 + k] = ai;
    }
    __syncthreads();
    if (t == 0) {
        int ssum = 0;
        for (int k = 0; k < 16; k++) ssum += shmi[k];
        int m = ssum % NPFR; if (m < 0) m += NPFR;
        sh_ifr = m;
    }
    __syncthreads();
    // spectral engram projection
    {
        const float* e = fr_emb + (layer * NPFR + sh_ifr) * ED;
        for (int u = t; u < 1024; u += 256) {        // u = c*16+k
            const float* W = fr_W + layer * ED * 1024 + u;
            float acc = fr_b[layer * 1024 + u];
#pragma unroll
            for (int j = 0; j < ED; j++) acc = fmaf(e[j], W[j * 1024], acc);
            shFR[u] = acc;
        }
    }
    __syncthreads();
    // gate-input means
    if (t < 64) {
        double acc = 0.0;
        const float* P = d_Pall + layer * NPSP * HID;
        for (int p = 0; p < NPSP; p++)
            acc += (double)hist[p] * (double)P[p * HID + t];
        shg[t]       = (float)(acc / (double)SS);
        shg[64 + t]  = shMHre[t * 16 + 0] / (float)SS;
        shg[128 + t] = shFR[t * 16 + 0] / (float)SS;
    }
    __syncthreads();
    if (t < 64) {
        float acc = gb1[layer * 64 + t];
        const float* W1 = gW1 + layer * 192 * 64;
        for (int j = 0; j < 192; j++) acc = fmaf(shg[j], W1[j * 64 + t], acc);
        shhid[t] = fmaxf(acc, 0.f);
    }
    __syncthreads();
    if (t == 0) {
        float lg[3];
        const float* W2 = gW2 + layer * 64 * 3;
        for (int o = 0; o < 3; o++) {
            float acc = gb2[layer * 3 + o];
            for (int j = 0; j < 64; j++) acc = fmaf(shhid[j], W2[j * 3 + o], acc);
            lg[o] = acc;
        }
        float mx = fmaxf(lg[0], fmaxf(lg[1], lg[2]));
        float e0 = expf(lg[0] - mx), e1 = expf(lg[1] - mx), e2 = expf(lg[2] - mx);
        float inv = 1.f / (e0 + e1 + e2);
        shw[0] = e0 * inv; shw[1] = e1 * inv; shw[2] = e2 * inv;
        d_gw[b] = shw[0];
    }
    __syncthreads();
    // combined, irfft-prescaled spectrum
    float w2 = shw[1], w3 = shw[2];
    for (int u = t; u < 1024; u += 256) {            // u = c*16+k
        int k = u & 15;
        int c = u >> 4;
        float sc = ((k == 0) ? 1.f : 2.f) / (float)SS;
        d_Cf[(b * HID + c) * 32 + k]      = (w2 * shMHre[u] + w3 * shFR[u]) * sc;
        d_Cf[(b * HID + c) * 32 + 16 + k] = (w2 * shMHim[u]) * sc;
    }
}

// ---------------- combine: h_next = gelu( w1*P[idx] + inverse-DFT ) ----------------
__global__ void __launch_bounds__(256) k_comb(int dst, int layer) {
    __shared__ float shC[HID * 32];
    float* hn = hbuf(dst);
    int b = blockIdx.y, chunk = blockIdx.x, t = threadIdx.x;
    for (int i = t; i < HID * 32 / 4; i += 256)
        *(float4*)&shC[i * 4] = *(const float4*)&d_Cf[b * HID * 32 + i * 4];
    __syncthreads();
    int s = chunk * 256 + t;
    float tc[16], tsn[16];
#pragma unroll
    for (int q = 0; q < 4; q++) {
        float4 vc = *(const float4*)&d_twc[s * NM + q * 4];
        float4 vs = *(const float4*)&d_tws[s * NM + q * 4];
        tc[q * 4 + 0] = vc.x; tc[q * 4 + 1] = vc.y; tc[q * 4 + 2] = vc.z; tc[q * 4 + 3] = vc.w;
        tsn[q * 4 + 0] = vs.x; tsn[q * 4 + 1] = vs.y; tsn[q * 4 + 2] = vs.z; tsn[q * 4 + 3] = vs.w;
    }
    int idxv = d_idx[b * SS + s];
    const float* Prow = d_Pall + (layer * NPSP + idxv) * HID;
    float w1 = d_gw[b];
#pragma unroll 2
    for (int c = 0; c < HID; c++) {
        const float* C = shC + c * 32;
        float inv = 0.f;
#pragma unroll
        for (int q = 0; q < 4; q++) {
            float4 cr = *(const float4*)&C[q * 4];
            float4 ci = *(const float4*)&C[16 + q * 4];
            inv = fmaf(cr.x, tc[q * 4 + 0], inv); inv = fmaf(-ci.x, tsn[q * 4 + 0], inv);
            inv = fmaf(cr.y, tc[q * 4 + 1], inv); inv = fmaf(-ci.y, tsn[q * 4 + 1], inv);
            inv = fmaf(cr.z, tc[q * 4 + 2], inv); inv = fmaf(-ci.z, tsn[q * 4 + 2], inv);
            inv = fmaf(cr.w, tc[q * 4 + 3], inv); inv = fmaf(-ci.w, tsn[q * 4 + 3], inv);
        }
        float v = fmaf(w1, Prow[c], inv);
        float gl = 0.5f * v * (1.f + erff(v * 0.70710678118654752f));
        hn[(b * HID + c) * SS + s] = gl;
    }
}

// ---------------- proj: out = h @ proj_W + proj_b ----------------
__global__ void k_proj(int src, const float* __restrict__ W, const float* __restrict__ bias,
                       float* __restrict__ out) {
    const float* h = hbuf_c(src);
    int i = blockIdx.x * 256 + threadIdx.x;          // B*S
    int b = i >> 14;
    int s = i & (SS - 1);
    float acc = bias[0];
    const float* hp = h + b * HID * SS + s;
#pragma unroll
    for (int c = 0; c < HID; c++) acc = fmaf(hp[c * SS], __ldg(&W[c]), acc);
    out[i] = acc;
}

// ---------------- host ----------------
extern "C" void kernel_launch(void* const* d_in, const int* in_sizes, int n_in,
                              void* d_out, int out_size) {
    const float* x      = (const float*)d_in[0];
    const float* lift_W = (const float*)d_in[1];
    const float* lift_b = (const float*)d_in[2];
    const float* proj_W = (const float*)d_in[3];
    const float* proj_b = (const float*)d_in[4];
    const float* sp_emb = (const float*)d_in[5];
    const float* sp_W   = (const float*)d_in[6];
    const float* sp_b   = (const float*)d_in[7];
    const float* fr_emb = (const float*)d_in[8];
    const float* fr_W   = (const float*)d_in[9];
    const float* fr_b   = (const float*)d_in[10];
    const float* gW1    = (const float*)d_in[11];
    const float* gb1    = (const float*)d_in[12];
    const float* gW2    = (const float*)d_in[13];
    const float* gb2    = (const float*)d_in[14];
    const float* mhf_Wr = (const float*)d_in[15];
    const float* mhf_Wi = (const float*)d_in[16];
    float* out = (float*)d_out;

    k_init_tw<<<(SS * NM) / 256, 256>>>();
    k_prep_all<<<(NL * NPSP * HID + 255) / 256, 256>>>(sp_emb, sp_W, sp_b);
    k_lift<<<(BB * SS) / 256, 256>>>(x, lift_W, lift_b);

    int src = 0;
    for (int layer = 0; layer < NL; layer++) {
        int dst = src ^ 1;
        k_fwd1<<<dim3(NCH, BB), 256>>>(src);
        k_mix<<<BB, 256>>>(fr_emb, fr_W, fr_b, mhf_Wr, mhf_Wi, gW1, gb1, gW2, gb2, layer);
        k_comb<<<dim3(64, BB), 256>>>(dst, layer);
        src = dst;
    }
    k_proj<<<(BB * SS) / 256, 256>>>(src, proj_W, proj_b, out);
}

// round 6
// speedup vs baseline: 1.5958x; 1.5958x over previous
#include <cuda_runtime.h>
#include <cuda_bf16.h>
#include <math.h>

#define BB   16
#define CIN  3
#define SS   16384
#define HID  64
#define NM   16
#define NL   4
#define NPSP 500
#define NPFR 200
#define ED   8
#define NCH  64          // split-K chunks for forward DFT (256 samples each)

// ---------------- scratch (__device__ globals; no allocation) ----------------
__device__ float d_hA[BB * HID * SS];            // 64 MB
__device__ float d_hB[BB * HID * SS];            // 64 MB
__device__ float d_twc[SS * NM];                 // [s][k] cos  (for k_comb)
__device__ float d_tws[SS * NM];                 // [s][k] sin
__device__ float d_twcT[NM * SS];                // [k][s] cos  (for k_fwd1)
__device__ float d_twsT[NM * SS];                // [k][s] sin
__device__ float d_part[BB * NCH * HID * 32];    // split-K partials, 8 MB
__device__ float d_Xf[BB * HID * 32];            // spectrum: 0..15 sum*cos (Re), 16..31 sum*sin (-Im)
__device__ float d_Cf[BB * HID * 32];            // combined scaled spectrum: 0..15 Re', 16..31 Im'
__device__ float d_sC[BB * SS];                  // per-position channel sums (for spatial hash)
__device__ int   d_idx[BB * SS];                 // spatial hash index
__device__ float d_Pall[NL * NPSP * HID];        // projected spatial patterns, all layers
__device__ float d_gw[BB];                       // gate weight w1 per batch

__device__ __forceinline__ const float* hbuf_c(int s) { return s ? d_hB : d_hA; }
__device__ __forceinline__ float*       hbuf(int s)   { return s ? d_hB : d_hA; }

// ---------------- twiddles (both layouts) ----------------
__global__ void k_init_tw() {
    int i = blockIdx.x * 256 + threadIdx.x;        // i < SS*NM
    int s = i / NM, k = i % NM;
    long m = ((long)s * (long)k) % SS;
    double th = 6.283185307179586476925286766559 * (double)m / (double)SS;
    float c = (float)cos(th), sn = (float)sin(th);
    d_twc[s * NM + k] = c;
    d_tws[s * NM + k] = sn;
    d_twcT[k * SS + s] = c;
    d_twsT[k * SS + s] = sn;
}

// ---------------- all-layer spatial pattern projection ----------------
__global__ void k_prep_all(const float* __restrict__ sp_emb, const float* __restrict__ sp_W,
                           const float* __restrict__ sp_b) {
    int i = blockIdx.x * 256 + threadIdx.x;        // NL*NPSP*HID = 128000
    if (i >= NL * NPSP * HID) return;
    int l = i / (NPSP * HID);
    int r = i - l * (NPSP * HID);
    int p = r / HID, c = r % HID;
    const float* e = sp_emb + (l * NPSP + p) * ED;
    const float* W = sp_W + l * ED * HID;
    float acc = sp_b[l * HID + c];
#pragma unroll
    for (int j = 0; j < ED; j++) acc = fmaf(e[j], W[j * HID + c], acc);
    d_Pall[i] = acc;
}

// ---------------- lift: h = x @ lift_W + lift_b  (+ channel sums for hash) ----------------
__global__ void k_lift(const float* __restrict__ x, const float* __restrict__ W,
                       const float* __restrict__ bias) {
    int i = blockIdx.x * 256 + threadIdx.x;        // over B*S
    int b = i >> 14;
    int s = i & (SS - 1);
    float x0 = x[(b * CIN + 0) * SS + s];
    float x1 = x[(b * CIN + 1) * SS + s];
    float x2 = x[(b * CIN + 2) * SS + s];
    float csum = 0.f;
#pragma unroll
    for (int c = 0; c < HID; c++) {
        float v = fmaf(x0, __ldg(&W[0 * HID + c]),
                  fmaf(x1, __ldg(&W[1 * HID + c]),
                  fmaf(x2, __ldg(&W[2 * HID + c]), __ldg(&bias[c]))));
        d_hA[(b * HID + c) * SS + s] = v;
        csum += v;
    }
    d_sC[b * SS + s] = csum;
}

// ---------------- forward DFT pass 1 (split-K, register-tiled) ----------------
// grid (NCH=64, B), 256 threads, 256 samples per block in 4 pieces of 64.
// Thread: g = t&15 -> cols {2g,2g+1}; c4 = t>>4 -> channels {4c4..4c4+3}.
// Both smem operands laid out [row][s] so fills are direct float4 copies and the
// inner loop is 6 LDS.128 per 32 FMA.
__global__ void __launch_bounds__(256) k_fwd1(int src) {
    __shared__ float sh_h[64][68];                 // [channel][s_local]
    __shared__ float sh_tw[32][68];                // [col][s_local] (0..15 cos, 16..31 sin)
    const float* h = hbuf_c(src);
    int chunk = blockIdx.x, b = blockIdx.y, t = threadIdx.x;
    int g = t & 15;
    int c4 = t >> 4;
    int s0 = chunk * 256;

    float a00 = 0.f, a01 = 0.f, a10 = 0.f, a11 = 0.f;
    float a20 = 0.f, a21 = 0.f, a30 = 0.f, a31 = 0.f;

    for (int piece = 0; piece < 4; piece++) {
        int sp0 = s0 + piece * 64;
        // h tile: 64 c x 64 s, direct float4 copy
        for (int u = t; u < 1024; u += 256) {
            int cc = u >> 4;
            int s4 = (u & 15) * 4;
            *(float4*)&sh_h[cc][s4] = *(const float4*)&h[(b * HID + cc) * SS + sp0 + s4];
        }
        // tw tile: 32 rows x 64 s, direct float4 copy from transposed twiddles
        for (int u = t; u < 512; u += 256) {
            int col = u >> 4;
            int s4 = (u & 15) * 4;
            float4 v;
            if (col < 16) v = *(const float4*)&d_twcT[col * SS + sp0 + s4];
            else          v = *(const float4*)&d_twsT[(col - 16) * SS + sp0 + s4];
            *(float4*)&sh_tw[col][s4] = v;
        }
        __syncthreads();
#pragma unroll
        for (int q = 0; q < 16; q++) {
            float4 t0 = *(const float4*)&sh_tw[g * 2 + 0][q * 4];
            float4 t1 = *(const float4*)&sh_tw[g * 2 + 1][q * 4];
            float4 hv;
            hv = *(const float4*)&sh_h[c4 * 4 + 0][q * 4];
            a00 = fmaf(hv.x, t0.x, fmaf(hv.y, t0.y, fmaf(hv.z, t0.z, fmaf(hv.w, t0.w, a00))));
            a01 = fmaf(hv.x, t1.x, fmaf(hv.y, t1.y, fmaf(hv.z, t1.z, fmaf(hv.w, t1.w, a01))));
            hv = *(const float4*)&sh_h[c4 * 4 + 1][q * 4];
            a10 = fmaf(hv.x, t0.x, fmaf(hv.y, t0.y, fmaf(hv.z, t0.z, fmaf(hv.w, t0.w, a10))));
            a11 = fmaf(hv.x, t1.x, fmaf(hv.y, t1.y, fmaf(hv.z, t1.z, fmaf(hv.w, t1.w, a11))));
            hv = *(const float4*)&sh_h[c4 * 4 + 2][q * 4];
            a20 = fmaf(hv.x, t0.x, fmaf(hv.y, t0.y, fmaf(hv.z, t0.z, fmaf(hv.w, t0.w, a20))));
            a21 = fmaf(hv.x, t1.x, fmaf(hv.y, t1.y, fmaf(hv.z, t1.z, fmaf(hv.w, t1.w, a21))));
            hv = *(const float4*)&sh_h[c4 * 4 + 3][q * 4];
            a30 = fmaf(hv.x, t0.x, fmaf(hv.y, t0.y, fmaf(hv.z, t0.z, fmaf(hv.w, t0.w, a30))));
            a31 = fmaf(hv.x, t1.x, fmaf(hv.y, t1.y, fmaf(hv.z, t1.z, fmaf(hv.w, t1.w, a31))));
        }
        __syncthreads();
    }
    float* p = &d_part[((b * NCH + chunk) * HID + c4 * 4) * 32 + g * 2];
    p[0 * 32 + 0] = a00; p[0 * 32 + 1] = a01;
    p[1 * 32 + 0] = a10; p[1 * 32 + 1] = a11;
    p[2 * 32 + 0] = a20; p[2 * 32 + 1] = a21;
    p[3 * 32 + 0] = a30; p[3 * 32 + 1] = a31;
}

// ---------------- forward DFT pass 2 (deterministic fp64 reduction) ----------------
__global__ void k_fwd2() {
    int i = blockIdx.x * 256 + threadIdx.x;        // B*HID*32 = 32768
    int b = i / (HID * 32);
    int rest = i - b * (HID * 32);
    const float* p = d_part + b * NCH * HID * 32 + rest;
    double acc = 0.0;
    for (int ch = 0; ch < NCH; ch++) acc += (double)p[ch * HID * 32];
    d_Xf[i] = (float)acc;
}

// ---------------- per-batch: spatial hash + spectral mix + gate + combined spectrum ----------------
__global__ void __launch_bounds__(256) k_mix(
        const float* __restrict__ fr_emb, const float* __restrict__ fr_W,
        const float* __restrict__ fr_b,
        const float* __restrict__ mhf_Wr, const float* __restrict__ mhf_Wi,
        const float* __restrict__ gW1, const float* __restrict__ gb1,
        const float* __restrict__ gW2, const float* __restrict__ gb2,
        int layer) {
    __shared__ float shX[HID * 32];
    __shared__ float shMHre[HID * NM];
    __shared__ float shMHim[HID * NM];
    __shared__ float shFR[HID * NM];
    __shared__ int   hist[NPSP];
    __shared__ float shg[192];
    __shared__ float shhid[64];
    __shared__ float shw[3];
    __shared__ int   shmi[16];
    __shared__ int   sh_ifr;
    int b = blockIdx.x, t = threadIdx.x;

    for (int i = t; i < NPSP; i += 256) hist[i] = 0;
    for (int i = t; i < HID * 32; i += 256) shX[i] = d_Xf[b * HID * 32 + i];
    __syncthreads();

    // spatial hash + histogram (int atomics in shared -> deterministic)
    {
        const float* sc = d_sC + b * SS;
        for (int s = t; s < SS; s += 256) {
            int a0 = max(s - 2, 0), a1 = max(s - 1, 0), a3 = min(s + 1, SS - 1);
            float w = ((sc[a0] + sc[a1]) + sc[s]) + sc[a3];
            int iv = (int)(w * 31.0f);
            int m = iv % NPSP; if (m < 0) m += NPSP;
            d_idx[b * SS + s] = m;
            atomicAdd(&hist[m], 1);
        }
    }

    // spectral magnitude hash (fixed channel order, fp64)
    if (t < 16) {
        double acc = 0.0;
        for (int c = 0; c < HID; c++) {
            double re = (double)shX[c * 32 + t];
            double im = (double)shX[c * 32 + 16 + t];
            acc += sqrt(re * re + im * im);
        }
        float mag = (float)(acc / 64.0);
        shmi[t] = (int)(mag * 1000.0f);
    }
    // multi-head Fourier mix
    for (int u = t; u < 1024; u += 256) {            // u = h*256 + o*16 + k
        int h_ = u >> 8, o = (u >> 4) & 15, k = u & 15;
        float ar = 0.f, ai = 0.f;
        const float* Wr = mhf_Wr + (((layer * 4 + h_) * 16) * 16 + o) * 16 + k;
        const float* Wi = mhf_Wi + (((layer * 4 + h_) * 16) * 16 + o) * 16 + k;
#pragma unroll
        for (int i = 0; i < 16; i++) {
            int cin = h_ * 16 + i;
            float re = shX[cin * 32 + k];
            float im = -shX[cin * 32 + 16 + k];
            float wr = Wr[i * 256];
            float wi = Wi[i * 256];
            ar = fmaf(re, wr, ar); ar = fmaf(-im, wi, ar);
            ai = fmaf(re, wi, ai); ai = fmaf(im, wr, ai);
        }
        int cout = h_ * 16 + o;
        shMHre[cout * 16 + k] = ar;
        shMHim[cout * 16 + k] = ai;
    }
    __syncthreads();
    if (t == 0) {
        int ssum = 0;
        for (int k = 0; k < 16; k++) ssum += shmi[k];
        int m = ssum % NPFR; if (m < 0) m += NPFR;
        sh_ifr = m;
    }
    __syncthreads();
    // spectral engram projection
    {
        const float* e = fr_emb + (layer * NPFR + sh_ifr) * ED;
        for (int u = t; u < 1024; u += 256) {        // u = c*16+k
            const float* W = fr_W + layer * ED * 1024 + u;
            float acc = fr_b[layer * 1024 + u];
#pragma unroll
            for (int j = 0; j < ED; j++) acc = fmaf(e[j], W[j * 1024], acc);
            shFR[u] = acc;
        }
    }
    __syncthreads();
    // gate-input means
    if (t < 64) {
        double acc = 0.0;
        const float* P = d_Pall + layer * NPSP * HID;
        for (int p = 0; p < NPSP; p++)
            acc += (double)hist[p] * (double)P[p * HID + t];
        shg[t]       = (float)(acc / (double)SS);
        shg[64 + t]  = shMHre[t * 16 + 0] / (float)SS;
        shg[128 + t] = shFR[t * 16 + 0] / (float)SS;
    }
    __syncthreads();
    if (t < 64) {
        float acc = gb1[layer * 64 + t];
        const float* W1 = gW1 + layer * 192 * 64;
        for (int j = 0; j < 192; j++) acc = fmaf(shg[j], W1[j * 64 + t], acc);
        shhid[t] = fmaxf(acc, 0.f);
    }
    __syncthreads();
    if (t == 0) {
        float lg[3];
        const float* W2 = gW2 + layer * 64 * 3;
        for (int o = 0; o < 3; o++) {
            float acc = gb2[layer * 3 + o];
            for (int j = 0; j < 64; j++) acc = fmaf(shhid[j], W2[j * 3 + o], acc);
            lg[o] = acc;
        }
        float mx = fmaxf(lg[0], fmaxf(lg[1], lg[2]));
        float e0 = expf(lg[0] - mx), e1 = expf(lg[1] - mx), e2 = expf(lg[2] - mx);
        float inv = 1.f / (e0 + e1 + e2);
        shw[0] = e0 * inv; shw[1] = e1 * inv; shw[2] = e2 * inv;
        d_gw[b] = shw[0];
    }
    __syncthreads();
    // combined, irfft-prescaled spectrum
    float w2 = shw[1], w3 = shw[2];
    for (int u = t; u < 1024; u += 256) {            // u = c*16+k
        int k = u & 15;
        int c = u >> 4;
        float sc = ((k == 0) ? 1.f : 2.f) / (float)SS;
        d_Cf[(b * HID + c) * 32 + k]      = (w2 * shMHre[u] + w3 * shFR[u]) * sc;
        d_Cf[(b * HID + c) * 32 + 16 + k] = (w2 * shMHim[u]) * sc;
    }
}

// ---------------- combine: h_next = gelu( w1*P[idx] + inverse-DFT ) ----------------
// Layers 0..2: write h + channel sums. Layer 3: fused projection, write out only.
__global__ void __launch_bounds__(256) k_comb(int dst, int layer,
                                              const float* __restrict__ projW,
                                              const float* __restrict__ projb,
                                              float* __restrict__ out) {
    __shared__ float shC[HID * 32];
    float* hn = hbuf(dst);
    int b = blockIdx.y, chunk = blockIdx.x, t = threadIdx.x;
    for (int i = t; i < HID * 32 / 4; i += 256)
        *(float4*)&shC[i * 4] = *(const float4*)&d_Cf[b * HID * 32 + i * 4];
    __syncthreads();
    int s = chunk * 256 + t;
    float tc[16], tsn[16];
#pragma unroll
    for (int q = 0; q < 4; q++) {
        float4 vc = *(const float4*)&d_twc[s * NM + q * 4];
        float4 vs = *(const float4*)&d_tws[s * NM + q * 4];
        tc[q * 4 + 0] = vc.x; tc[q * 4 + 1] = vc.y; tc[q * 4 + 2] = vc.z; tc[q * 4 + 3] = vc.w;
        tsn[q * 4 + 0] = vs.x; tsn[q * 4 + 1] = vs.y; tsn[q * 4 + 2] = vs.z; tsn[q * 4 + 3] = vs.w;
    }
    int idxv = d_idx[b * SS + s];
    const float* Prow = d_Pall + (layer * NPSP + idxv) * HID;
    float w1 = d_gw[b];
    bool last = (layer == NL - 1);
    float csum = 0.f, pacc = 0.f;
#pragma unroll 2
    for (int c = 0; c < HID; c++) {
        const float* C = shC + c * 32;
        float inv = 0.f;
#pragma unroll
        for (int q = 0; q < 4; q++) {
            float4 cr = *(const float4*)&C[q * 4];
            float4 ci = *(const float4*)&C[16 + q * 4];
            inv = fmaf(cr.x, tc[q * 4 + 0], inv); inv = fmaf(-ci.x, tsn[q * 4 + 0], inv);
            inv = fmaf(cr.y, tc[q * 4 + 1], inv); inv = fmaf(-ci.y, tsn[q * 4 + 1], inv);
            inv = fmaf(cr.z, tc[q * 4 + 2], inv); inv = fmaf(-ci.z, tsn[q * 4 + 2], inv);
            inv = fmaf(cr.w, tc[q * 4 + 3], inv); inv = fmaf(-ci.w, tsn[q * 4 + 3], inv);
        }
        float v = fmaf(w1, Prow[c], inv);
        float gl = 0.5f * v * (1.f + erff(v * 0.70710678118654752f));
        if (last) {
            pacc = fmaf(gl, __ldg(&projW[c]), pacc);
        } else {
            hn[(b * HID + c) * SS + s] = gl;
            csum += gl;
        }
    }
    if (last) out[b * SS + s] = pacc + projb[0];
    else      d_sC[b * SS + s] = csum;
}

// ---------------- host ----------------
extern "C" void kernel_launch(void* const* d_in, const int* in_sizes, int n_in,
                              void* d_out, int out_size) {
    const float* x      = (const float*)d_in[0];
    const float* lift_W = (const float*)d_in[1];
    const float* lift_b = (const float*)d_in[2];
    const float* proj_W = (const float*)d_in[3];
    const float* proj_b = (const float*)d_in[4];
    const float* sp_emb = (const float*)d_in[5];
    const float* sp_W   = (const float*)d_in[6];
    const float* sp_b   = (const float*)d_in[7];
    const float* fr_emb = (const float*)d_in[8];
    const float* fr_W   = (const float*)d_in[9];
    const float* fr_b   = (const float*)d_in[10];
    const float* gW1    = (const float*)d_in[11];
    const float* gb1    = (const float*)d_in[12];
    const float* gW2    = (const float*)d_in[13];
    const float* gb2    = (const float*)d_in[14];
    const float* mhf_Wr = (const float*)d_in[15];
    const float* mhf_Wi = (const float*)d_in[16];
    float* out = (float*)d_out;

    k_init_tw<<<(SS * NM) / 256, 256>>>();
    k_prep_all<<<(NL * NPSP * HID + 255) / 256, 256>>>(sp_emb, sp_W, sp_b);
    k_lift<<<(BB * SS) / 256, 256>>>(x, lift_W, lift_b);

    int src = 0;
    for (int layer = 0; layer < NL; layer++) {
        int dst = src ^ 1;
        k_fwd1<<<dim3(NCH, BB), 256>>>(src);
        k_fwd2<<<(BB * HID * 32) / 256, 256>>>();
        k_mix<<<BB, 256>>>(fr_emb, fr_W, fr_b, mhf_Wr, mhf_Wi, gW1, gb1, gW2, gb2, layer);
        k_comb<<<dim3(64, BB), 256>>>(dst, layer, proj_W, proj_b, out);
        src = dst;
    }
}

// round 8
// speedup vs baseline: 2.3913x; 1.4985x over previous
#include <cuda_runtime.h>
#include <cuda_bf16.h>
#include <math.h>

#define BB   16
#define CIN  3
#define SS   16384
#define HID  64
#define NM   16
#define NL   4
#define NPSP 500
#define NPFR 200
#define ED   8
#define NCH  64          // split-K chunks for forward DFT (256 samples each)

// ---------------- scratch (__device__ globals; no allocation) ----------------
__device__ float d_hA[BB * HID * SS];            // 64 MB
__device__ float d_hB[BB * HID * SS];            // 64 MB
__device__ float d_twcT[NM * SS];                // [k][s] cos
__device__ float d_twsT[NM * SS];                // [k][s] sin
__device__ float d_part[BB * NCH * HID * 32];    // split-K partials, 8 MB
__device__ float d_Xf[BB * HID * 32];            // spectrum: 0..15 sum*cos (Re), 16..31 sum*sin (-Im)
__device__ float d_Cf[BB * HID * 32];            // combined scaled spectrum: 0..15 Re', 16..31 Im'
__device__ float d_sC[BB * SS];                  // per-position channel sums (for spatial hash)
__device__ int   d_idx[BB * SS];                 // spatial hash index
__device__ int   d_cnt[BB * NPSP];               // per-batch global histogram
__device__ float d_Pall[NL * NPSP * HID];        // projected spatial patterns, all layers
__device__ float d_gw[BB];                       // gate weight w1 per batch

__device__ __forceinline__ const float* hbuf_c(int s) { return s ? d_hB : d_hA; }
__device__ __forceinline__ float*       hbuf(int s)   { return s ? d_hB : d_hA; }

// ---------------- twiddles ----------------
__global__ void k_init_tw() {
    int i = blockIdx.x * 256 + threadIdx.x;        // i < SS*NM
    int s = i / NM, k = i % NM;
    long m = ((long)s * (long)k) % SS;
    double th = 6.283185307179586476925286766559 * (double)m / (double)SS;
    d_twcT[k * SS + s] = (float)cos(th);
    d_twsT[k * SS + s] = (float)sin(th);
}

// ---------------- all-layer spatial pattern projection ----------------
__global__ void k_prep_all(const float* __restrict__ sp_emb, const float* __restrict__ sp_W,
                           const float* __restrict__ sp_b) {
    int i = blockIdx.x * 256 + threadIdx.x;        // NL*NPSP*HID = 128000
    if (i >= NL * NPSP * HID) return;
    int l = i / (NPSP * HID);
    int r = i - l * (NPSP * HID);
    int p = r / HID, c = r % HID;
    const float* e = sp_emb + (l * NPSP + p) * ED;
    const float* W = sp_W + l * ED * HID;
    float acc = sp_b[l * HID + c];
#pragma unroll
    for (int j = 0; j < ED; j++) acc = fmaf(e[j], W[j * HID + c], acc);
    d_Pall[i] = acc;
}

// ---------------- lift: h = x @ lift_W + lift_b  (+ channel sums for hash) ----------------
__global__ void k_lift(const float* __restrict__ x, const float* __restrict__ W,
                       const float* __restrict__ bias) {
    int i = blockIdx.x * 256 + threadIdx.x;        // over B*S
    int b = i >> 14;
    int s = i & (SS - 1);
    float x0 = x[(b * CIN + 0) * SS + s];
    float x1 = x[(b * CIN + 1) * SS + s];
    float x2 = x[(b * CIN + 2) * SS + s];
    float csum = 0.f;
#pragma unroll
    for (int c = 0; c < HID; c++) {
        float v = fmaf(x0, __ldg(&W[0 * HID + c]),
                  fmaf(x1, __ldg(&W[1 * HID + c]),
                  fmaf(x2, __ldg(&W[2 * HID + c]), __ldg(&bias[c]))));
        d_hA[(b * HID + c) * SS + s] = v;
        csum += v;
    }
    d_sC[b * SS + s] = csum;
}

// ---------------- forward DFT pass 1 (split-K, register-tiled) ----------------
// grid (NCH=64, B), 256 threads, 256 samples per block in 4 pieces of 64.
__global__ void __launch_bounds__(256) k_fwd1(int src) {
    __shared__ float sh_h[64][68];                 // [channel][s_local]
    __shared__ float sh_tw[32][68];                // [col][s_local] (0..15 cos, 16..31 sin)
    const float* h = hbuf_c(src);
    int chunk = blockIdx.x, b = blockIdx.y, t = threadIdx.x;
    int g = t & 15;
    int c4 = t >> 4;
    int s0 = chunk * 256;

    float a00 = 0.f, a01 = 0.f, a10 = 0.f, a11 = 0.f;
    float a20 = 0.f, a21 = 0.f, a30 = 0.f, a31 = 0.f;

    for (int piece = 0; piece < 4; piece++) {
        int sp0 = s0 + piece * 64;
        for (int u = t; u < 1024; u += 256) {
            int cc = u >> 4;
            int s4 = (u & 15) * 4;
            *(float4*)&sh_h[cc][s4] = *(const float4*)&h[(b * HID + cc) * SS + sp0 + s4];
        }
        for (int u = t; u < 512; u += 256) {
            int col = u >> 4;
            int s4 = (u & 15) * 4;
            float4 v;
            if (col < 16) v = *(const float4*)&d_twcT[col * SS + sp0 + s4];
            else          v = *(const float4*)&d_twsT[(col - 16) * SS + sp0 + s4];
            *(float4*)&sh_tw[col][s4] = v;
        }
        __syncthreads();
#pragma unroll
        for (int q = 0; q < 16; q++) {
            float4 t0 = *(const float4*)&sh_tw[g * 2 + 0][q * 4];
            float4 t1 = *(const float4*)&sh_tw[g * 2 + 1][q * 4];
            float4 hv;
            hv = *(const float4*)&sh_h[c4 * 4 + 0][q * 4];
            a00 = fmaf(hv.x, t0.x, fmaf(hv.y, t0.y, fmaf(hv.z, t0.z, fmaf(hv.w, t0.w, a00))));
            a01 = fmaf(hv.x, t1.x, fmaf(hv.y, t1.y, fmaf(hv.z, t1.z, fmaf(hv.w, t1.w, a01))));
            hv = *(const float4*)&sh_h[c4 * 4 + 1][q * 4];
            a10 = fmaf(hv.x, t0.x, fmaf(hv.y, t0.y, fmaf(hv.z, t0.z, fmaf(hv.w, t0.w, a10))));
            a11 = fmaf(hv.x, t1.x, fmaf(hv.y, t1.y, fmaf(hv.z, t1.z, fmaf(hv.w, t1.w, a11))));
            hv = *(const float4*)&sh_h[c4 * 4 + 2][q * 4];
            a20 = fmaf(hv.x, t0.x, fmaf(hv.y, t0.y, fmaf(hv.z, t0.z, fmaf(hv.w, t0.w, a20))));
            a21 = fmaf(hv.x, t1.x, fmaf(hv.y, t1.y, fmaf(hv.z, t1.z, fmaf(hv.w, t1.w, a21))));
            hv = *(const float4*)&sh_h[c4 * 4 + 3][q * 4];
            a30 = fmaf(hv.x, t0.x, fmaf(hv.y, t0.y, fmaf(hv.z, t0.z, fmaf(hv.w, t0.w, a30))));
            a31 = fmaf(hv.x, t1.x, fmaf(hv.y, t1.y, fmaf(hv.z, t1.z, fmaf(hv.w, t1.w, a31))));
        }
        __syncthreads();
    }
    float* p = &d_part[((b * NCH + chunk) * HID + c4 * 4) * 32 + g * 2];
    p[0 * 32 + 0] = a00; p[0 * 32 + 1] = a01;
    p[1 * 32 + 0] = a10; p[1 * 32 + 1] = a11;
    p[2 * 32 + 0] = a20; p[2 * 32 + 1] = a21;
    p[3 * 32 + 0] = a30; p[3 * 32 + 1] = a31;
}

// ---------------- forward DFT pass 2 (deterministic fp64 reduction) + d_cnt zero ----------------
__global__ void k_fwd2() {
    int i = blockIdx.x * 256 + threadIdx.x;        // B*HID*32 = 32768
    if (i < BB * NPSP) d_cnt[i] = 0;
    int b = i / (HID * 32);
    int rest = i - b * (HID * 32);
    const float* p = d_part + b * NCH * HID * 32 + rest;
    double acc = 0.0;
#pragma unroll 8
    for (int ch = 0; ch < NCH; ch++) acc += (double)p[ch * HID * 32];
    d_Xf[i] = (float)acc;
}

// ---------------- spatial hash + histogram (1024 blocks; int atomics = deterministic) ----------------
__global__ void __launch_bounds__(256) k_hash() {
    __shared__ int hist[NPSP];
    int b = blockIdx.y, chunk = blockIdx.x, t = threadIdx.x;
    for (int i = t; i < NPSP; i += 256) hist[i] = 0;
    __syncthreads();
    int s = chunk * 256 + t;
    const float* sc = d_sC + b * SS;
    int a0 = max(s - 2, 0), a1 = max(s - 1, 0), a3 = min(s + 1, SS - 1);
    float w = ((sc[a0] + sc[a1]) + sc[s]) + sc[a3];
    int iv = (int)(w * 31.0f);
    int m = iv % NPSP; if (m < 0) m += NPSP;
    d_idx[b * SS + s] = m;
    atomicAdd(&hist[m], 1);
    __syncthreads();
    for (int i = t; i < NPSP; i += 256)
        if (hist[i]) atomicAdd(&d_cnt[b * NPSP + i], hist[i]);
}

// ---------------- per-batch: spectral mix + gate + combined spectrum ----------------
__global__ void __launch_bounds__(256) k_mix(
        const float* __restrict__ fr_emb, const float* __restrict__ fr_W,
        const float* __restrict__ fr_b,
        const float* __restrict__ mhf_Wr, const float* __restrict__ mhf_Wi,
        const float* __restrict__ gW1, const float* __restrict__ gb1,
        const float* __restrict__ gW2, const float* __restrict__ gb2,
        int layer) {
    __shared__ float shX[HID * 32];
    __shared__ float shMHre[HID * NM];
    __shared__ float shMHim[HID * NM];
    __shared__ float shFR[HID * NM];
    __shared__ double shmagp[4][16];
    __shared__ double shgp[4][64];
    __shared__ float shg[192];
    __shared__ float shhid[64];
    __shared__ float shw[3];
    __shared__ int   shmi[16];
    __shared__ int   sh_ifr;
    int b = blockIdx.x, t = threadIdx.x;

    for (int i = t; i < HID * 32; i += 256) shX[i] = d_Xf[b * HID * 32 + i];
    __syncthreads();

    // spectral magnitude hash: 4 fixed-order fp64 slices of 16 channels
    if (t < 64) {
        int k = t & 15, sl = t >> 4;
        double acc = 0.0;
        for (int c = sl * 16; c < sl * 16 + 16; c++) {
            double re = (double)shX[c * 32 + k];
            double im = (double)shX[c * 32 + 16 + k];
            acc += sqrt(re * re + im * im);
        }
        shmagp[sl][k] = acc;
    }
    // multi-head Fourier mix
    for (int u = t; u < 1024; u += 256) {            // u = h*256 + o*16 + k
        int h_ = u >> 8, o = (u >> 4) & 15, k = u & 15;
        float ar = 0.f, ai = 0.f;
        const float* Wr = mhf_Wr + (((layer * 4 + h_) * 16) * 16 + o) * 16 + k;
        const float* Wi = mhf_Wi + (((layer * 4 + h_) * 16) * 16 + o) * 16 + k;
#pragma unroll
        for (int i = 0; i < 16; i++) {
            int cin = h_ * 16 + i;
            float re = shX[cin * 32 + k];
            float im = -shX[cin * 32 + 16 + k];
            float wr = Wr[i * 256];
            float wi = Wi[i * 256];
            ar = fmaf(re, wr, ar); ar = fmaf(-im, wi, ar);
            ai = fmaf(re, wi, ai); ai = fmaf(im, wr, ai);
        }
        int cout = h_ * 16 + o;
        shMHre[cout * 16 + k] = ar;
        shMHim[cout * 16 + k] = ai;
    }
    __syncthreads();
    if (t < 16) {
        double acc = ((shmagp[0][t] + shmagp[1][t]) + shmagp[2][t]) + shmagp[3][t];
        float mag = (float)(acc / 64.0);
        shmi[t] = (int)(mag * 1000.0f);
    }
    __syncthreads();
    if (t == 0) {
        int ssum = 0;
        for (int k = 0; k < 16; k++) ssum += shmi[k];
        int m = ssum % NPFR; if (m < 0) m += NPFR;
        sh_ifr = m;
    }
    __syncthreads();
    // spectral engram projection
    {
        const float* e = fr_emb + (layer * NPFR + sh_ifr) * ED;
        for (int u = t; u < 1024; u += 256) {        // u = c*16+k
            const float* W = fr_W + layer * ED * 1024 + u;
            float acc = fr_b[layer * 1024 + u];
#pragma unroll
            for (int j = 0; j < ED; j++) acc = fmaf(e[j], W[j * 1024], acc);
            shFR[u] = acc;
        }
    }
    // gate spatial mean: 4 fixed-order fp64 slices of 125 patterns
    {
        int c = t & 63, sl = t >> 6;
        double acc = 0.0;
        const float* P = d_Pall + layer * NPSP * HID;
        const int* cnt = d_cnt + b * NPSP;
        for (int p = sl * 125; p < sl * 125 + 125; p++)
            acc += (double)cnt[p] * (double)P[p * HID + c];
        shgp[sl][c] = acc;
    }
    __syncthreads();
    if (t < 64) {
        double acc = ((shgp[0][t] + shgp[1][t]) + shgp[2][t]) + shgp[3][t];
        shg[t]       = (float)(acc / (double)SS);
        shg[64 + t]  = shMHre[t * 16 + 0] / (float)SS;
        shg[128 + t] = shFR[t * 16 + 0] / (float)SS;
    }
    __syncthreads();
    if (t < 64) {
        float acc = gb1[layer * 64 + t];
        const float* W1 = gW1 + layer * 192 * 64;
        for (int j = 0; j < 192; j++) acc = fmaf(shg[j], W1[j * 64 + t], acc);
        shhid[t] = fmaxf(acc, 0.f);
    }
    __syncthreads();
    if (t == 0) {
        float lg[3];
        const float* W2 = gW2 + layer * 64 * 3;
        for (int o = 0; o < 3; o++) {
            float acc = gb2[layer * 3 + o];
            for (int j = 0; j < 64; j++) acc = fmaf(shhid[j], W2[j * 3 + o], acc);
            lg[o] = acc;
        }
        float mx = fmaxf(lg[0], fmaxf(lg[1], lg[2]));
        float e0 = expf(lg[0] - mx), e1 = expf(lg[1] - mx), e2 = expf(lg[2] - mx);
        float inv = 1.f / (e0 + e1 + e2);
        shw[0] = e0 * inv; shw[1] = e1 * inv; shw[2] = e2 * inv;
        d_gw[b] = shw[0];
    }
    __syncthreads();
    // combined, irfft-prescaled spectrum
    float w2 = shw[1], w3 = shw[2];
    for (int u = t; u < 1024; u += 256) {            // u = c*16+k
        int k = u & 15;
        int c = u >> 4;
        float sc = ((k == 0) ? 1.f : 2.f) / (float)SS;
        d_Cf[(b * HID + c) * 32 + k]      = (w2 * shMHre[u] + w3 * shFR[u]) * sc;
        d_Cf[(b * HID + c) * 32 + 16 + k] = (w2 * shMHim[u]) * sc;
    }
}

// ---------------- combine (GEMM-structured inverse DFT + engram + gelu) ----------------
// h[c][s] = gelu( w1*P[idx[s]][c] + sum_K A[K][c]*T[K][s] ),  A = [Cr | -Ci], T = [cos | sin].
// Thread tile: 4 channels (c4) x 4 samples (sg). Layers 0..2 write h + channel sums;
// layer 3 fuses the output projection.
__global__ void __launch_bounds__(256) k_comb(int dst, int layer,
                                              const float* __restrict__ projW,
                                              const float* __restrict__ projb,
                                              float* __restrict__ out) {
    __shared__ float shA[32][68];                  // [K][channel]
    __shared__ float shT[32][68];                  // [K][s_local]
    __shared__ float shCS[16 * 64];                // per-c4 partial channel sums
    float* hn = hbuf(dst);
    int b = blockIdx.y, chunk = blockIdx.x, t = threadIdx.x;
    int sg = t & 15, c4 = t >> 4;
    int s0 = chunk * 256;
    bool last = (layer == NL - 1);

    for (int u = t; u < 2048; u += 256) {
        int K = u >> 6, c = u & 63;
        float v = (K < 16) ? d_Cf[b * 2048 + c * 32 + K]
                           : -d_Cf[b * 2048 + c * 32 + 16 + (K - 16)];
        shA[K][c] = v;
    }
    float w1 = d_gw[b];
    float pw0 = 1.f, pw1 = 1.f, pw2 = 1.f, pw3 = 1.f;
    if (last) {
        pw0 = __ldg(&projW[c4 * 4 + 0]); pw1 = __ldg(&projW[c4 * 4 + 1]);
        pw2 = __ldg(&projW[c4 * 4 + 2]); pw3 = __ldg(&projW[c4 * 4 + 3]);
    }

    for (int piece = 0; piece < 4; piece++) {
        int sp0 = s0 + piece * 64;
        for (int u = t; u < 512; u += 256) {
            int K = u >> 4, s4 = (u & 15) * 4;
            float4 v;
            if (K < 16) v = *(const float4*)&d_twcT[K * SS + sp0 + s4];
            else        v = *(const float4*)&d_twsT[(K - 16) * SS + sp0 + s4];
            *(float4*)&shT[K][s4] = v;
        }
        __syncthreads();

        float acc[4][4];
#pragma unroll
        for (int ci = 0; ci < 4; ci++)
#pragma unroll
            for (int si = 0; si < 4; si++) acc[ci][si] = 0.f;

#pragma unroll
        for (int K = 0; K < 32; K++) {
            float4 a  = *(const float4*)&shA[K][c4 * 4];
            float4 tv = *(const float4*)&shT[K][sg * 4];
            acc[0][0] = fmaf(a.x, tv.x, acc[0][0]); acc[0][1] = fmaf(a.x, tv.y, acc[0][1]);
            acc[0][2] = fmaf(a.x, tv.z, acc[0][2]); acc[0][3] = fmaf(a.x, tv.w, acc[0][3]);
            acc[1][0] = fmaf(a.y, tv.x, acc[1][0]); acc[1][1] = fmaf(a.y, tv.y, acc[1][1]);
            acc[1][2] = fmaf(a.y, tv.z, acc[1][2]); acc[1][3] = fmaf(a.y, tv.w, acc[1][3]);
            acc[2][0] = fmaf(a.z, tv.x, acc[2][0]); acc[2][1] = fmaf(a.z, tv.y, acc[2][1]);
            acc[2][2] = fmaf(a.z, tv.z, acc[2][2]); acc[2][3] = fmaf(a.z, tv.w, acc[2][3]);
            acc[3][0] = fmaf(a.w, tv.x, acc[3][0]); acc[3][1] = fmaf(a.w, tv.y, acc[3][1]);
            acc[3][2] = fmaf(a.w, tv.z, acc[3][2]); acc[3][3] = fmaf(a.w, tv.w, acc[3][3]);
        }

        // epilogue: engram add + exact gelu + partial channel/proj sums
        int4 iv = *(const int4*)&d_idx[b * SS + sp0 + sg * 4];
        int ids[4] = {iv.x, iv.y, iv.z, iv.w};
        float ps[4];
#pragma unroll
        for (int si = 0; si < 4; si++) {
            float4 P = *(const float4*)&d_Pall[(layer * NPSP + ids[si]) * HID + c4 * 4];
            float v0 = fmaf(w1, P.x, acc[0][si]);
            float v1 = fmaf(w1, P.y, acc[1][si]);
            float v2 = fmaf(w1, P.z, acc[2][si]);
            float v3 = fmaf(w1, P.w, acc[3][si]);
            float g0 = 0.5f * v0 * (1.f + erff(v0 * 0.70710678118654752f));
            float g1 = 0.5f * v1 * (1.f + erff(v1 * 0.70710678118654752f));
            float g2 = 0.5f * v2 * (1.f + erff(v2 * 0.70710678118654752f));
            float g3 = 0.5f * v3 * (1.f + erff(v3 * 0.70710678118654752f));
            acc[0][si] = g0; acc[1][si] = g1; acc[2][si] = g2; acc[3][si] = g3;
            ps[si] = fmaf(g0, pw0, fmaf(g1, pw1, fmaf(g2, pw2, g3 * pw3)));
        }
        if (!last) {
#pragma unroll
            for (int ci = 0; ci < 4; ci++) {
                float4 st = make_float4(acc[ci][0], acc[ci][1], acc[ci][2], acc[ci][3]);
                *(float4*)&hn[(b * HID + c4 * 4 + ci) * SS + sp0 + sg * 4] = st;
            }
        }
        *(float4*)&shCS[c4 * 64 + sg * 4] = make_float4(ps[0], ps[1], ps[2], ps[3]);
        __syncthreads();
        if (t < 64) {
            float ss = 0.f;
#pragma unroll
            for (int q = 0; q < 16; q++) ss += shCS[q * 64 + t];   // fixed order
            if (last) out[b * SS + sp0 + t] = ss + projb[0];
            else      d_sC[b * SS + sp0 + t] = ss;
        }
        __syncthreads();
    }
}

// ---------------- host ----------------
extern "C" void kernel_launch(void* const* d_in, const int* in_sizes, int n_in,
                              void* d_out, int out_size) {
    const float* x      = (const float*)d_in[0];
    const float* lift_W = (const float*)d_in[1];
    const float* lift_b = (const float*)d_in[2];
    const float* proj_W = (const float*)d_in[3];
    const float* proj_b = (const float*)d_in[4];
    const float* sp_emb = (const float*)d_in[5];
    const float* sp_W   = (const float*)d_in[6];
    const float* sp_b   = (const float*)d_in[7];
    const float* fr_emb = (const float*)d_in[8];
    const float* fr_W   = (const float*)d_in[9];
    const float* fr_b   = (const float*)d_in[10];
    const float* gW1    = (const float*)d_in[11];
    const float* gb1    = (const float*)d_in[12];
    const float* gW2    = (const float*)d_in[13];
    const float* gb2    = (const float*)d_in[14];
    const float* mhf_Wr = (const float*)d_in[15];
    const float* mhf_Wi = (const float*)d_in[16];
    float* out = (float*)d_out;

    k_init_tw<<<(SS * NM) / 256, 256>>>();
    k_prep_all<<<(NL * NPSP * HID + 255) / 256, 256>>>(sp_emb, sp_W, sp_b);
    k_lift<<<(BB * SS) / 256, 256>>>(x, lift_W, lift_b);

    int src = 0;
    for (int layer = 0; layer < NL; layer++) {
        int dst = src ^ 1;
        k_fwd1<<<dim3(NCH, BB), 256>>>(src);
        k_fwd2<<<(BB * HID * 32) / 256, 256>>>();
        k_hash<<<dim3(64, BB), 256>>>();
        k_mix<<<BB, 256>>>(fr_emb, fr_W, fr_b, mhf_Wr, mhf_Wi, gW1, gb1, gW2, gb2, layer);
        k_comb<<<dim3(64, BB), 256>>>(dst, layer, proj_W, proj_b, out);
        src = dst;
    }
}